// round 1
// baseline (speedup 1.0000x reference)
#include <cuda_runtime.h>
#include <cstdio>

#define D 64
#define NMAX 100000

// ---------------- scratch (static device globals; no runtime alloc) ----------------
__device__ float g_emb[NMAX * D];
__device__ float g_h[NMAX * D];    // h (GCN) then h2 (GAT)
__device__ float g_acc[NMAX * D];  // segment-sum accumulator (GCN then GAT)
__device__ float g_x[NMAX * D];    // GCN output x, then diffused
__device__ float g_deg[NMAX];
__device__ float g_as[NMAX];
__device__ float g_ad[NMAX];
__device__ float g_z[NMAX];

// ---------------- helpers ----------------
__device__ __forceinline__ float4 f4fma(float a, float4 b, float4 c) {
    c.x = fmaf(a, b.x, c.x); c.y = fmaf(a, b.y, c.y);
    c.z = fmaf(a, b.z, c.z); c.w = fmaf(a, b.w, c.w);
    return c;
}
__device__ __forceinline__ void red4(float* addr, float4 v) {
    asm volatile("red.global.add.v4.f32 [%0], {%1,%2,%3,%4};"
                 :: "l"(addr), "f"(v.x), "f"(v.y), "f"(v.z), "f"(v.w) : "memory");
}
__device__ __forceinline__ float sigmoidf_(float x) { return 1.0f / (1.0f + __expf(-x)); }

// ---------------- K0: deg init (self-loop = 1) ----------------
__global__ void k_init_deg(int n) {
    int i = blockIdx.x * blockDim.x + threadIdx.x;
    if (i < n) g_deg[i] = 1.0f;
}

// ---------------- K2: degree accumulation over edges ----------------
__global__ void k_deg(const int* __restrict__ ei, int E) {
    int e = blockIdx.x * blockDim.x + threadIdx.x;
    if (e < E) atomicAdd(&g_deg[ei[E + e]], 1.0f);
}

// ---------------- K1: event encoder (fused 2-layer MLP) ----------------
__global__ void k_encoder(const float* __restrict__ ev,
                          const float* __restrict__ W1, const float* __restrict__ b1,
                          const float* __restrict__ W2, const float* __restrict__ b2, int n) {
    __shared__ __align__(16) float evs[16][8];
    __shared__ float4 W1s[8][16];
    __shared__ float4 W2s[64][16];
    __shared__ float t1s[16][64];

    int tid = threadIdx.x;
    int r = tid >> 4, c4 = tid & 15;
    int row0 = blockIdx.x * 16;
    int row = row0 + r;

    if (tid < 128) {
        int rr = tid >> 3, cc = tid & 7;
        int gr = row0 + rr;
        evs[rr][cc] = (gr < n) ? ev[gr * 8 + cc] : 0.0f;
        W1s[tid >> 4][tid & 15] = ((const float4*)W1)[tid];
    }
    for (int i = tid; i < 1024; i += 256) W2s[i >> 4][i & 15] = ((const float4*)W2)[i];
    __syncthreads();

    float4 acc = ((const float4*)b1)[c4];
#pragma unroll
    for (int k = 0; k < 8; k++) acc = f4fma(evs[r][k], W1s[k][c4], acc);
    t1s[r][c4 * 4 + 0] = fmaxf(acc.x, 0.f);
    t1s[r][c4 * 4 + 1] = fmaxf(acc.y, 0.f);
    t1s[r][c4 * 4 + 2] = fmaxf(acc.z, 0.f);
    t1s[r][c4 * 4 + 3] = fmaxf(acc.w, 0.f);
    __syncthreads();

    float4 a2 = ((const float4*)b2)[c4];
#pragma unroll 16
    for (int k = 0; k < 64; k++) a2 = f4fma(t1s[r][k], W2s[k][c4], a2);
    if (row < n) ((float4*)g_emb)[row * 16 + c4] = a2;
}

// ---------------- K3/K7: [n,64]x[64,64] GEMM (mode 0: emb->h, mode 1: x->h) ----------------
__global__ void k_gemm64(int mode, const float* __restrict__ W, int n) {
    __shared__ __align__(16) float Xs[16][64];
    __shared__ float4 Ws[64][16];
    int tid = threadIdx.x;
    int r = tid >> 4, c4 = tid & 15;
    int row0 = blockIdx.x * 16;
    int row = row0 + r;
    const float* X = mode ? g_x : g_emb;

    {
        int rr = tid >> 4, cc = tid & 15;
        int gr = row0 + rr;
        float4 v = make_float4(0.f, 0.f, 0.f, 0.f);
        if (gr < n) v = ((const float4*)X)[gr * 16 + cc];
        *(float4*)&Xs[rr][cc * 4] = v;
    }
    for (int i = tid; i < 1024; i += 256) Ws[i >> 4][i & 15] = ((const float4*)W)[i];
    __syncthreads();

    float4 acc = make_float4(0.f, 0.f, 0.f, 0.f);
#pragma unroll 16
    for (int k = 0; k < 64; k++) acc = f4fma(Xs[r][k], Ws[k][c4], acc);
    if (row < n) ((float4*)g_h)[row * 16 + c4] = acc;
}

// ---------------- K4: GCN accumulator init with self-loop term ----------------
__global__ void k_gcn_init(int n) {
    int idx = blockIdx.x * blockDim.x + threadIdx.x;
    int node = idx >> 4, c4 = idx & 15;
    if (node >= n) return;
    float dinv = rsqrtf(g_deg[node]);
    float s = dinv * dinv;
    float4 v = ((const float4*)g_h)[node * 16 + c4];
    v.x *= s; v.y *= s; v.z *= s; v.w *= s;
    ((float4*)g_acc)[node * 16 + c4] = v;
}

// ---------------- K5: GCN edge scatter (16 lanes per edge) ----------------
__global__ void k_gcn_scatter(const int* __restrict__ ei, int E) {
    long long t = (long long)blockIdx.x * blockDim.x + threadIdx.x;
    int e = (int)(t >> 4), j = (int)(t & 15);
    if (e >= E) return;
    int s = ei[e], d = ei[E + e];
    float norm = rsqrtf(g_deg[s]) * rsqrtf(g_deg[d]);
    float4 v = ((const float4*)g_h)[s * 16 + j];
    v.x *= norm; v.y *= norm; v.z *= norm; v.w *= norm;
    red4(&g_acc[d * 64 + j * 4], v);
}

// ---------------- K6: x = relu(acc + gcn_b) ----------------
__global__ void k_gcn_fin(const float* __restrict__ b, int n) {
    int idx = blockIdx.x * blockDim.x + threadIdx.x;
    int node = idx >> 4, c4 = idx & 15;
    if (node >= n) return;
    float4 v = ((const float4*)g_acc)[node * 16 + c4];
    float4 bb = ((const float4*)b)[c4];
    v.x = fmaxf(v.x + bb.x, 0.f); v.y = fmaxf(v.y + bb.y, 0.f);
    v.z = fmaxf(v.z + bb.z, 0.f); v.w = fmaxf(v.w + bb.w, 0.f);
    ((float4*)g_x)[node * 16 + c4] = v;
}

// ---------------- K8: GAT per-node: a_s, a_d, self-loop seed (warp per node) ----------------
__global__ void k_gat_node(const float* __restrict__ att_s, const float* __restrict__ att_d, int n) {
    int gt = blockIdx.x * blockDim.x + threadIdx.x;
    int node = gt >> 5;
    int lane = gt & 31;
    if (node >= n) return;
    float h0 = g_h[node * 64 + lane];
    float h1 = g_h[node * 64 + 32 + lane];
    float as = h0 * att_s[lane] + h1 * att_s[32 + lane];
    float ad = h0 * att_d[lane] + h1 * att_d[32 + lane];
#pragma unroll
    for (int o = 16; o; o >>= 1) {
        as += __shfl_xor_sync(0xffffffffu, as, o);
        ad += __shfl_xor_sync(0xffffffffu, ad, o);
    }
    float e = as + ad;
    float lr = e > 0.f ? e : 0.2f * e;
    float w = __expf(lr);
    if (lane == 0) { g_as[node] = as; g_ad[node] = ad; g_z[node] = w; }
    g_acc[node * 64 + lane] = h0 * w;
    g_acc[node * 64 + 32 + lane] = h1 * w;
}

// ---------------- K9: GAT edge scatter (16 lanes per edge; unnormalized softmax) ----------------
__global__ void k_gat_scatter(const int* __restrict__ ei, int E) {
    long long t = (long long)blockIdx.x * blockDim.x + threadIdx.x;
    int e = (int)(t >> 4), j = (int)(t & 15);
    if (e >= E) return;
    int s = ei[e], d = ei[E + e];
    float ev = g_as[s] + g_ad[d];
    float lr = ev > 0.f ? ev : 0.2f * ev;
    float w = __expf(lr);
    if (j == 0) atomicAdd(&g_z[d], w);
    float4 v = ((const float4*)g_h)[s * 16 + j];
    v.x *= w; v.y *= w; v.z *= w; v.w *= w;
    red4(&g_acc[d * 64 + j * 4], v);
}

// ---------------- K10a: diffused = relu(acc / z + gat_b) ----------------
__global__ void k_gat_fin(const float* __restrict__ b, int n) {
    int idx = blockIdx.x * blockDim.x + threadIdx.x;
    int node = idx >> 4, c4 = idx & 15;
    if (node >= n) return;
    float inv = 1.0f / g_z[node];
    float4 v = ((const float4*)g_acc)[node * 16 + c4];
    float4 bb = ((const float4*)b)[c4];
    v.x = fmaxf(fmaf(v.x, inv, bb.x), 0.f);
    v.y = fmaxf(fmaf(v.y, inv, bb.y), 0.f);
    v.z = fmaxf(fmaf(v.z, inv, bb.z), 0.f);
    v.w = fmaxf(fmaf(v.w, inv, bb.w), 0.f);
    ((float4*)g_x)[node * 16 + c4] = v;
}

// ---------------- K10: fused gate + residual + speed head ----------------
// dynamic smem: fus[16][128] (2048 f) | Wb 2048 float4 (8192 f) | gb[16][64] | tb[16][64]
__global__ void k_final(const float* __restrict__ H,
                        const float* __restrict__ gate_W, const float* __restrict__ gate_b,
                        const float* __restrict__ res_W1, const float* __restrict__ res_b1,
                        const float* __restrict__ res_W2, const float* __restrict__ res_b2,
                        const float* __restrict__ sp_W1, const float* __restrict__ sp_b1,
                        const float* __restrict__ sp_W2, const float* __restrict__ sp_b2,
                        float* __restrict__ delta_out, float* __restrict__ hf_out,
                        float* __restrict__ pred_out, int n) {
    extern __shared__ float sm[];
    float* fus = sm;                       // 2048 floats
    float4* Wb = (float4*)(sm + 2048);     // 2048 float4 = 8192 floats
    float* gb = sm + 2048 + 8192;          // 1024 floats
    float* tb = gb + 1024;                 // 1024 floats

    int tid = threadIdx.x;
    int r = tid >> 4, c4 = tid & 15;
    int row0 = blockIdx.x * 16;
    int row = row0 + r;

    // load fusion = [H | diffused]
    for (int i = tid; i < 512; i += 256) {
        int rr = i >> 5, j = i & 31;
        int gr = row0 + rr;
        float4 v = make_float4(0.f, 0.f, 0.f, 0.f);
        if (gr < n) v = (j < 16) ? ((const float4*)H)[gr * 16 + j]
                                 : ((const float4*)g_x)[gr * 16 + (j - 16)];
        *(float4*)&fus[rr * 128 + j * 4] = v;
    }
    // gate_W
    for (int i = tid; i < 2048; i += 256) Wb[i] = ((const float4*)gate_W)[i];
    __syncthreads();

    float4 acc = ((const float4*)gate_b)[c4];
#pragma unroll 16
    for (int k = 0; k < 128; k++) acc = f4fma(fus[r * 128 + k], Wb[k * 16 + c4], acc);
    gb[r * 64 + c4 * 4 + 0] = sigmoidf_(acc.x);
    gb[r * 64 + c4 * 4 + 1] = sigmoidf_(acc.y);
    gb[r * 64 + c4 * 4 + 2] = sigmoidf_(acc.z);
    gb[r * 64 + c4 * 4 + 3] = sigmoidf_(acc.w);
    __syncthreads();

    // res_W1
    for (int i = tid; i < 2048; i += 256) Wb[i] = ((const float4*)res_W1)[i];
    __syncthreads();
    acc = ((const float4*)res_b1)[c4];
#pragma unroll 16
    for (int k = 0; k < 128; k++) acc = f4fma(fus[r * 128 + k], Wb[k * 16 + c4], acc);
    tb[r * 64 + c4 * 4 + 0] = fmaxf(acc.x, 0.f);
    tb[r * 64 + c4 * 4 + 1] = fmaxf(acc.y, 0.f);
    tb[r * 64 + c4 * 4 + 2] = fmaxf(acc.z, 0.f);
    tb[r * 64 + c4 * 4 + 3] = fmaxf(acc.w, 0.f);
    __syncthreads();

    // res_W2
    for (int i = tid; i < 1024; i += 256) Wb[i] = ((const float4*)res_W2)[i];
    __syncthreads();
    acc = ((const float4*)res_b2)[c4];
#pragma unroll 16
    for (int k = 0; k < 64; k++) acc = f4fma(tb[r * 64 + k], Wb[k * 16 + c4], acc);

    float4 g4 = *(float4*)&gb[r * 64 + c4 * 4];
    float4 h4 = *(float4*)&fus[r * 128 + c4 * 4];
    float4 d4 = make_float4(g4.x * acc.x, g4.y * acc.y, g4.z * acc.z, g4.w * acc.w);
    float4 hf4 = make_float4(h4.x + d4.x, h4.y + d4.y, h4.z + d4.z, h4.w + d4.w);
    if (row < n) {
        ((float4*)delta_out)[row * 16 + c4] = d4;
        ((float4*)hf_out)[row * 16 + c4] = hf4;
    }
    *(float4*)&fus[r * 128 + c4 * 4] = hf4;  // owner slot; reused for speed head
    __syncthreads();

    // sp_W1 [64,32]
    for (int i = tid; i < 512; i += 256) Wb[i] = ((const float4*)sp_W1)[i];
    __syncthreads();
    {
        const float* Wf = (const float*)Wb;
        float a0 = sp_b1[c4 * 2], a1 = sp_b1[c4 * 2 + 1];
#pragma unroll 16
        for (int k = 0; k < 64; k++) {
            float hv = fus[r * 128 + k];
            a0 = fmaf(hv, Wf[k * 32 + c4 * 2], a0);
            a1 = fmaf(hv, Wf[k * 32 + c4 * 2 + 1], a1);
        }
        tb[r * 32 + c4 * 2] = fmaxf(a0, 0.f);
        tb[r * 32 + c4 * 2 + 1] = fmaxf(a1, 0.f);
    }
    __syncthreads();
    if (tid < 16) {
        int gr = row0 + tid;
        if (gr < n) {
            float a = sp_b2[0];
#pragma unroll
            for (int k = 0; k < 32; k++) a = fmaf(tb[tid * 32 + k], sp_W2[k], a);
            pred_out[gr] = a;
        }
    }
}

// ---------------- launch ----------------
extern "C" void kernel_launch(void* const* d_in, const int* in_sizes, int n_in,
                              void* d_out, int out_size) {
    const float* H       = (const float*)d_in[0];
    const float* ev      = (const float*)d_in[1];
    const int*   ei      = (const int*)d_in[2];
    const float* enc_W1  = (const float*)d_in[3];
    const float* enc_b1  = (const float*)d_in[4];
    const float* enc_W2  = (const float*)d_in[5];
    const float* enc_b2  = (const float*)d_in[6];
    const float* gcn_W   = (const float*)d_in[7];
    const float* gcn_b   = (const float*)d_in[8];
    const float* gat_W   = (const float*)d_in[9];
    const float* att_s   = (const float*)d_in[10];
    const float* att_d   = (const float*)d_in[11];
    const float* gat_b   = (const float*)d_in[12];
    const float* gate_W  = (const float*)d_in[13];
    const float* gate_b  = (const float*)d_in[14];
    const float* res_W1  = (const float*)d_in[15];
    const float* res_b1  = (const float*)d_in[16];
    const float* res_W2  = (const float*)d_in[17];
    const float* res_b2  = (const float*)d_in[18];
    const float* sp_W1   = (const float*)d_in[19];
    const float* sp_b1   = (const float*)d_in[20];
    const float* sp_W2   = (const float*)d_in[21];
    const float* sp_b2   = (const float*)d_in[22];

    int n = in_sizes[0] / 64;
    int E = in_sizes[2] / 2;

    float* delta = (float*)d_out;
    float* hf    = delta + (size_t)n * 64;
    float* pred  = hf + (size_t)n * 64;

    int nb16  = (n + 15) / 16;                       // 16-row node tiles
    int nbN   = (n + 255) / 256;
    int nb16t = (n * 16 + 255) / 256;                // node*16 threads
    int nbE   = (E + 255) / 256;
    long long et = (long long)E * 16;
    int nbE16 = (int)((et + 255) / 256);
    int nbW   = (n * 32 + 255) / 256;                // warp per node

    static bool attr_set = false;
    if (!attr_set) {
        cudaFuncSetAttribute(k_final, cudaFuncAttributeMaxDynamicSharedMemorySize, 49152);
        attr_set = true;
    }

    k_init_deg<<<nbN, 256>>>(n);
    k_deg<<<nbE, 256>>>(ei, E);
    k_encoder<<<nb16, 256>>>(ev, enc_W1, enc_b1, enc_W2, enc_b2, n);
    k_gemm64<<<nb16, 256>>>(0, gcn_W, n);            // h = emb @ gcn_W
    k_gcn_init<<<nb16t, 256>>>(n);
    k_gcn_scatter<<<nbE16, 256>>>(ei, E);
    k_gcn_fin<<<nb16t, 256>>>(gcn_b, n);             // x
    k_gemm64<<<nb16, 256>>>(1, gat_W, n);            // h2 = x @ gat_W
    k_gat_node<<<nbW, 256>>>(att_s, att_d, n);
    k_gat_scatter<<<nbE16, 256>>>(ei, E);
    k_gat_fin<<<nb16t, 256>>>(gat_b, n);             // diffused
    k_final<<<nb16, 256, 49152>>>(H, gate_W, gate_b, res_W1, res_b1, res_W2, res_b2,
                                  sp_W1, sp_b1, sp_W2, sp_b2, delta, hf, pred, n);
}

// round 2
// speedup vs baseline: 1.7501x; 1.7501x over previous
#include <cuda_runtime.h>

#define D 64
#define NMAX 100000
#define EMAX 1600000

// ---------------- scratch (static device globals) ----------------
__device__ float g_h[NMAX * D];    // h (GCN) then h2 (GAT)
__device__ float g_x[NMAX * D];    // GCN output x, then diffused
__device__ float g_as[NMAX];
__device__ float g_ad[NMAX];
__device__ float g_dinv[NMAX];
__device__ int   g_cnt[NMAX];
__device__ int   g_rs[NMAX];
__device__ int   g_cur[NMAX];
__device__ int   g_bsum[256];
__device__ int   g_csrc[EMAX];

// ---------------- helpers ----------------
__device__ __forceinline__ float4 f4fma(float a, float4 b, float4 c) {
    c.x = fmaf(a, b.x, c.x); c.y = fmaf(a, b.y, c.y);
    c.z = fmaf(a, b.z, c.z); c.w = fmaf(a, b.w, c.w);
    return c;
}
__device__ __forceinline__ float sigmoidf_(float x) { return 1.0f / (1.0f + __expf(-x)); }

// ---------------- CSR build ----------------
__global__ void k_zero(int n) {
    int i = blockIdx.x * blockDim.x + threadIdx.x;
    if (i < n) g_cnt[i] = 0;
}
__global__ void k_cnt(const int* __restrict__ ei, int E) {
    int e = blockIdx.x * blockDim.x + threadIdx.x;
    if (e < E) atomicAdd(&g_cnt[ei[E + e]], 1);
}
__global__ void k_scanA(int n) {
    __shared__ int s[1024];
    int tid = threadIdx.x;
    int i = blockIdx.x * 1024 + tid;
    int v = (i < n) ? g_cnt[i] : 0;
    s[tid] = v; __syncthreads();
    for (int off = 1; off < 1024; off <<= 1) {
        int t = (tid >= off) ? s[tid - off] : 0;
        __syncthreads();
        s[tid] += t; __syncthreads();
    }
    if (i < n) g_rs[i] = s[tid] - v;
    if (tid == 1023) g_bsum[blockIdx.x] = s[1023];
}
__global__ void k_scanB(int nb) {
    __shared__ int s[128];
    int tid = threadIdx.x;
    int v = (tid < nb) ? g_bsum[tid] : 0;
    s[tid] = v; __syncthreads();
    for (int off = 1; off < 128; off <<= 1) {
        int t = (tid >= off) ? s[tid - off] : 0;
        __syncthreads();
        s[tid] += t; __syncthreads();
    }
    if (tid < nb) g_bsum[tid] = s[tid] - v;
}
__global__ void k_scanC(int n) {
    int i = blockIdx.x * blockDim.x + threadIdx.x;
    if (i >= n) return;
    int base = g_bsum[i >> 10];
    int r = g_rs[i] + base;
    g_rs[i] = r;
    g_cur[i] = r;
    g_dinv[i] = rsqrtf((float)g_cnt[i] + 1.0f);  // deg includes self-loop
}
__global__ void k_csr(const int* __restrict__ ei, int E) {
    int e = blockIdx.x * blockDim.x + threadIdx.x;
    if (e >= E) return;
    int s = ei[e], d = ei[E + e];
    int p = atomicAdd(&g_cur[d], 1);
    g_csrc[p] = s;
}

// ---------------- fused encoder MLP + GCN weight GEMM (64-row tile, 4 rows/thread) ----
// smem: evs[64][9] | t1[64][65] | t2[64][65] | Wb[1024] float4
__global__ void k_encgemm(const float* __restrict__ ev,
                          const float* __restrict__ W1, const float* __restrict__ b1,
                          const float* __restrict__ W2, const float* __restrict__ b2,
                          const float* __restrict__ gcnW, int n) {
    extern __shared__ float sm[];
    float* evs = sm;                    // 64*9 = 576
    float* t1  = sm + 576;              // 64*65 = 4160
    float* t2  = t1 + 4160;             // 4160
    float4* Wb = (float4*)(t2 + 4160);  // 1024 float4

    int tid = threadIdx.x;
    int c4 = tid & 15, rq = tid >> 4;
    int row0 = blockIdx.x * 64;

    for (int i = tid; i < 512; i += 256) {
        int rr = i >> 3, cc = i & 7;
        int gr = row0 + rr;
        evs[rr * 9 + cc] = (gr < n) ? ev[gr * 8 + cc] : 0.0f;
    }
    if (tid < 128) Wb[tid] = ((const float4*)W1)[tid];
    __syncthreads();

    float4 a[4];
#pragma unroll
    for (int m = 0; m < 4; m++) a[m] = ((const float4*)b1)[c4];
#pragma unroll
    for (int k = 0; k < 8; k++) {
        float4 w = Wb[k * 16 + c4];
#pragma unroll
        for (int m = 0; m < 4; m++) a[m] = f4fma(evs[(rq + 16 * m) * 9 + k], w, a[m]);
    }
#pragma unroll
    for (int m = 0; m < 4; m++) {
        int rm = rq + 16 * m;
        t1[rm * 65 + c4 * 4 + 0] = fmaxf(a[m].x, 0.f);
        t1[rm * 65 + c4 * 4 + 1] = fmaxf(a[m].y, 0.f);
        t1[rm * 65 + c4 * 4 + 2] = fmaxf(a[m].z, 0.f);
        t1[rm * 65 + c4 * 4 + 3] = fmaxf(a[m].w, 0.f);
    }
    __syncthreads();
    for (int i = tid; i < 1024; i += 256) Wb[i] = ((const float4*)W2)[i];
    __syncthreads();

#pragma unroll
    for (int m = 0; m < 4; m++) a[m] = ((const float4*)b2)[c4];
#pragma unroll 16
    for (int k = 0; k < 64; k++) {
        float4 w = Wb[k * 16 + c4];
#pragma unroll
        for (int m = 0; m < 4; m++) a[m] = f4fma(t1[(rq + 16 * m) * 65 + k], w, a[m]);
    }
#pragma unroll
    for (int m = 0; m < 4; m++) {
        int rm = rq + 16 * m;
        t2[rm * 65 + c4 * 4 + 0] = a[m].x;
        t2[rm * 65 + c4 * 4 + 1] = a[m].y;
        t2[rm * 65 + c4 * 4 + 2] = a[m].z;
        t2[rm * 65 + c4 * 4 + 3] = a[m].w;
    }
    __syncthreads();
    for (int i = tid; i < 1024; i += 256) Wb[i] = ((const float4*)gcnW)[i];
    __syncthreads();

#pragma unroll
    for (int m = 0; m < 4; m++) a[m] = make_float4(0.f, 0.f, 0.f, 0.f);
#pragma unroll 16
    for (int k = 0; k < 64; k++) {
        float4 w = Wb[k * 16 + c4];
#pragma unroll
        for (int m = 0; m < 4; m++) a[m] = f4fma(t2[(rq + 16 * m) * 65 + k], w, a[m]);
    }
#pragma unroll
    for (int m = 0; m < 4; m++) {
        int row = row0 + rq + 16 * m;
        if (row < n) ((float4*)g_h)[row * 16 + c4] = a[m];
    }
}

// ---------------- [n,64]x[64,64] GEMM: g_x @ W -> g_h (64-row tile, 4 rows/thread) ----
__global__ void k_gemm64v2(const float* __restrict__ W, int n) {
    __shared__ float Xs[64 * 65];
    __shared__ float4 Ws[1024];
    int tid = threadIdx.x;
    int c4 = tid & 15, rq = tid >> 4;
    int row0 = blockIdx.x * 64;

    for (int i = tid; i < 1024; i += 256) {
        int rr = i >> 4, cc = i & 15;
        int gr = row0 + rr;
        float4 v = make_float4(0.f, 0.f, 0.f, 0.f);
        if (gr < n) v = ((const float4*)g_x)[gr * 16 + cc];
        int base = rr * 65 + cc * 4;
        Xs[base] = v.x; Xs[base + 1] = v.y; Xs[base + 2] = v.z; Xs[base + 3] = v.w;
    }
    for (int i = tid; i < 1024; i += 256) Ws[i] = ((const float4*)W)[i];
    __syncthreads();

    float4 a[4];
#pragma unroll
    for (int m = 0; m < 4; m++) a[m] = make_float4(0.f, 0.f, 0.f, 0.f);
#pragma unroll 16
    for (int k = 0; k < 64; k++) {
        float4 w = Ws[k * 16 + c4];
#pragma unroll
        for (int m = 0; m < 4; m++) a[m] = f4fma(Xs[(rq + 16 * m) * 65 + k], w, a[m]);
    }
#pragma unroll
    for (int m = 0; m < 4; m++) {
        int row = row0 + rq + 16 * m;
        if (row < n) ((float4*)g_h)[row * 16 + c4] = a[m];
    }
}

// ---------------- GCN pull aggregation (warp per node, no atomics) ----------------
__global__ void k_gcn_agg(const float* __restrict__ b, int n) {
    int gt = blockIdx.x * blockDim.x + threadIdx.x;
    int d = gt >> 5, lane = gt & 31;
    if (d >= n) return;
    const float2* H2 = (const float2*)g_h;
    float dinv_d = g_dinv[d];
    float2 hv = H2[d * 32 + lane];
    float sn = dinv_d * dinv_d;
    float accx = hv.x * sn, accy = hv.y * sn;
    int beg = g_rs[d], cnt = g_cnt[d];
    for (int c0 = 0; c0 < cnt; c0 += 32) {
        int idx = c0 + lane;
        int s = 0; float nm = 0.f;
        if (idx < cnt) { s = g_csrc[beg + idx]; nm = g_dinv[s] * dinv_d; }
        int m = min(32, cnt - c0);
#pragma unroll 8
        for (int j = 0; j < m; j++) {
            int sj = __shfl_sync(0xffffffffu, s, j);
            float nj = __shfl_sync(0xffffffffu, nm, j);
            float2 h2 = H2[sj * 32 + lane];
            accx = fmaf(nj, h2.x, accx);
            accy = fmaf(nj, h2.y, accy);
        }
    }
    float2 bb = ((const float2*)b)[lane];
    float2 o;
    o.x = fmaxf(accx + bb.x, 0.f);
    o.y = fmaxf(accy + bb.y, 0.f);
    ((float2*)g_x)[d * 32 + lane] = o;
}

// ---------------- GAT per-node attention coefficients ----------------
__global__ void k_gat_node(const float* __restrict__ att_s, const float* __restrict__ att_d, int n) {
    int gt = blockIdx.x * blockDim.x + threadIdx.x;
    int node = gt >> 5, lane = gt & 31;
    if (node >= n) return;
    float h0 = g_h[node * 64 + lane];
    float h1 = g_h[node * 64 + 32 + lane];
    float as = h0 * att_s[lane] + h1 * att_s[32 + lane];
    float ad = h0 * att_d[lane] + h1 * att_d[32 + lane];
#pragma unroll
    for (int o = 16; o; o >>= 1) {
        as += __shfl_xor_sync(0xffffffffu, as, o);
        ad += __shfl_xor_sync(0xffffffffu, ad, o);
    }
    if (lane == 0) { g_as[node] = as; g_ad[node] = ad; }
}

// ---------------- GAT pull aggregation (warp per node, softmax without max-shift) ----
__global__ void k_gat_agg(const float* __restrict__ b, int n) {
    int gt = blockIdx.x * blockDim.x + threadIdx.x;
    int d = gt >> 5, lane = gt & 31;
    if (d >= n) return;
    const float2* H2 = (const float2*)g_h;
    float ad_d = g_ad[d];
    float e0 = g_as[d] + ad_d;
    float l0 = e0 > 0.f ? e0 : 0.2f * e0;
    float wself = __expf(l0);
    float2 hd = H2[d * 32 + lane];
    float accx = wself * hd.x, accy = wself * hd.y;
    float zp = (lane == 0) ? wself : 0.f;
    int beg = g_rs[d], cnt = g_cnt[d];
    for (int c0 = 0; c0 < cnt; c0 += 32) {
        int idx = c0 + lane;
        int s = 0; float w = 0.f;
        if (idx < cnt) {
            s = g_csrc[beg + idx];
            float ev = g_as[s] + ad_d;
            float lr = ev > 0.f ? ev : 0.2f * ev;
            w = __expf(lr);
        }
        zp += w;
        int m = min(32, cnt - c0);
#pragma unroll 8
        for (int j = 0; j < m; j++) {
            int sj = __shfl_sync(0xffffffffu, s, j);
            float wj = __shfl_sync(0xffffffffu, w, j);
            float2 h2 = H2[sj * 32 + lane];
            accx = fmaf(wj, h2.x, accx);
            accy = fmaf(wj, h2.y, accy);
        }
    }
#pragma unroll
    for (int o = 16; o; o >>= 1) zp += __shfl_xor_sync(0xffffffffu, zp, o);
    float inv = 1.0f / zp;
    float2 bb = ((const float2*)b)[lane];
    float2 o2;
    o2.x = fmaxf(fmaf(accx, inv, bb.x), 0.f);
    o2.y = fmaxf(fmaf(accy, inv, bb.y), 0.f);
    ((float2*)g_x)[d * 32 + lane] = o2;
}

// ---------------- fused gate + residual + speed head (64-row tile, 4 rows/thread) ----
// dyn smem: fus[64][129] | Wb 2048 float4 | gb[64][65] | tb[64][65]
__global__ void k_final(const float* __restrict__ H,
                        const float* __restrict__ gate_W, const float* __restrict__ gate_b,
                        const float* __restrict__ res_W1, const float* __restrict__ res_b1,
                        const float* __restrict__ res_W2, const float* __restrict__ res_b2,
                        const float* __restrict__ sp_W1, const float* __restrict__ sp_b1,
                        const float* __restrict__ sp_W2, const float* __restrict__ sp_b2,
                        float* __restrict__ delta_out, float* __restrict__ hf_out,
                        float* __restrict__ pred_out, int n) {
    extern __shared__ float sm[];
    float* fus = sm;                          // 64*129 = 8256
    float* gb  = sm + 8256;                   // 64*65 = 4160
    float* tb  = gb + 4160;                   // 4160
    float4* Wb = (float4*)(tb + 4160);        // 2048 float4

    int tid = threadIdx.x;
    int c4 = tid & 15, rq = tid >> 4;
    int row0 = blockIdx.x * 64;

    for (int i = tid; i < 2048; i += 256) {
        int rr = i >> 5, j = i & 31;
        int gr = row0 + rr;
        float4 v = make_float4(0.f, 0.f, 0.f, 0.f);
        if (gr < n) v = (j < 16) ? ((const float4*)H)[gr * 16 + j]
                                 : ((const float4*)g_x)[gr * 16 + (j - 16)];
        int base = rr * 129 + j * 4;
        fus[base] = v.x; fus[base + 1] = v.y; fus[base + 2] = v.z; fus[base + 3] = v.w;
    }
    for (int i = tid; i < 2048; i += 256) Wb[i] = ((const float4*)gate_W)[i];
    __syncthreads();

    float4 a[4];
    // gate
#pragma unroll
    for (int m = 0; m < 4; m++) a[m] = ((const float4*)gate_b)[c4];
#pragma unroll 16
    for (int k = 0; k < 128; k++) {
        float4 w = Wb[k * 16 + c4];
#pragma unroll
        for (int m = 0; m < 4; m++) a[m] = f4fma(fus[(rq + 16 * m) * 129 + k], w, a[m]);
    }
#pragma unroll
    for (int m = 0; m < 4; m++) {
        int rm = rq + 16 * m;
        gb[rm * 65 + c4 * 4 + 0] = sigmoidf_(a[m].x);
        gb[rm * 65 + c4 * 4 + 1] = sigmoidf_(a[m].y);
        gb[rm * 65 + c4 * 4 + 2] = sigmoidf_(a[m].z);
        gb[rm * 65 + c4 * 4 + 3] = sigmoidf_(a[m].w);
    }
    __syncthreads();
    for (int i = tid; i < 2048; i += 256) Wb[i] = ((const float4*)res_W1)[i];
    __syncthreads();

    // res layer 1
#pragma unroll
    for (int m = 0; m < 4; m++) a[m] = ((const float4*)res_b1)[c4];
#pragma unroll 16
    for (int k = 0; k < 128; k++) {
        float4 w = Wb[k * 16 + c4];
#pragma unroll
        for (int m = 0; m < 4; m++) a[m] = f4fma(fus[(rq + 16 * m) * 129 + k], w, a[m]);
    }
#pragma unroll
    for (int m = 0; m < 4; m++) {
        int rm = rq + 16 * m;
        tb[rm * 65 + c4 * 4 + 0] = fmaxf(a[m].x, 0.f);
        tb[rm * 65 + c4 * 4 + 1] = fmaxf(a[m].y, 0.f);
        tb[rm * 65 + c4 * 4 + 2] = fmaxf(a[m].z, 0.f);
        tb[rm * 65 + c4 * 4 + 3] = fmaxf(a[m].w, 0.f);
    }
    __syncthreads();
    for (int i = tid; i < 1024; i += 256) Wb[i] = ((const float4*)res_W2)[i];
    __syncthreads();

    // res layer 2 + delta + H_final
#pragma unroll
    for (int m = 0; m < 4; m++) a[m] = ((const float4*)res_b2)[c4];
#pragma unroll 16
    for (int k = 0; k < 64; k++) {
        float4 w = Wb[k * 16 + c4];
#pragma unroll
        for (int m = 0; m < 4; m++) a[m] = f4fma(tb[(rq + 16 * m) * 65 + k], w, a[m]);
    }
#pragma unroll
    for (int m = 0; m < 4; m++) {
        int rm = rq + 16 * m;
        int row = row0 + rm;
        float g0 = gb[rm * 65 + c4 * 4 + 0], g1 = gb[rm * 65 + c4 * 4 + 1];
        float g2 = gb[rm * 65 + c4 * 4 + 2], g3 = gb[rm * 65 + c4 * 4 + 3];
        float h0 = fus[rm * 129 + c4 * 4 + 0], h1 = fus[rm * 129 + c4 * 4 + 1];
        float h2 = fus[rm * 129 + c4 * 4 + 2], h3 = fus[rm * 129 + c4 * 4 + 3];
        float4 d4 = make_float4(g0 * a[m].x, g1 * a[m].y, g2 * a[m].z, g3 * a[m].w);
        float4 hf4 = make_float4(h0 + d4.x, h1 + d4.y, h2 + d4.z, h3 + d4.w);
        if (row < n) {
            ((float4*)delta_out)[row * 16 + c4] = d4;
            ((float4*)hf_out)[row * 16 + c4] = hf4;
        }
        // reuse gb as H_final storage for speed head
        gb[rm * 65 + c4 * 4 + 0] = hf4.x;
        gb[rm * 65 + c4 * 4 + 1] = hf4.y;
        gb[rm * 65 + c4 * 4 + 2] = hf4.z;
        gb[rm * 65 + c4 * 4 + 3] = hf4.w;
    }
    __syncthreads();
    for (int i = tid; i < 512; i += 256) Wb[i] = ((const float4*)sp_W1)[i];
    __syncthreads();

    // speed head layer 1: cols c4*2, c4*2+1
    {
        const float* Wf = (const float*)Wb;
        float s0[4], s1[4];
#pragma unroll
        for (int m = 0; m < 4; m++) { s0[m] = sp_b1[c4 * 2]; s1[m] = sp_b1[c4 * 2 + 1]; }
#pragma unroll 8
        for (int k = 0; k < 64; k++) {
            float w0 = Wf[k * 32 + c4 * 2], w1 = Wf[k * 32 + c4 * 2 + 1];
#pragma unroll
            for (int m = 0; m < 4; m++) {
                float hv = gb[(rq + 16 * m) * 65 + k];
                s0[m] = fmaf(hv, w0, s0[m]);
                s1[m] = fmaf(hv, w1, s1[m]);
            }
        }
#pragma unroll
        for (int m = 0; m < 4; m++) {
            int rm = rq + 16 * m;
            tb[rm * 65 + c4 * 2] = fmaxf(s0[m], 0.f);
            tb[rm * 65 + c4 * 2 + 1] = fmaxf(s1[m], 0.f);
        }
    }
    __syncthreads();
    if (tid < 64) {
        int gr = row0 + tid;
        if (gr < n) {
            float acc = sp_b2[0];
#pragma unroll
            for (int k = 0; k < 32; k++) acc = fmaf(tb[tid * 65 + k], sp_W2[k], acc);
            pred_out[gr] = acc;
        }
    }
}

// ---------------- launch ----------------
extern "C" void kernel_launch(void* const* d_in, const int* in_sizes, int n_in,
                              void* d_out, int out_size) {
    const float* H      = (const float*)d_in[0];
    const float* ev     = (const float*)d_in[1];
    const int*   ei     = (const int*)d_in[2];
    const float* enc_W1 = (const float*)d_in[3];
    const float* enc_b1 = (const float*)d_in[4];
    const float* enc_W2 = (const float*)d_in[5];
    const float* enc_b2 = (const float*)d_in[6];
    const float* gcn_W  = (const float*)d_in[7];
    const float* gcn_b  = (const float*)d_in[8];
    const float* gat_W  = (const float*)d_in[9];
    const float* att_s  = (const float*)d_in[10];
    const float* att_d  = (const float*)d_in[11];
    const float* gat_b  = (const float*)d_in[12];
    const float* gate_W = (const float*)d_in[13];
    const float* gate_b = (const float*)d_in[14];
    const float* res_W1 = (const float*)d_in[15];
    const float* res_b1 = (const float*)d_in[16];
    const float* res_W2 = (const float*)d_in[17];
    const float* res_b2 = (const float*)d_in[18];
    const float* sp_W1  = (const float*)d_in[19];
    const float* sp_b1  = (const float*)d_in[20];
    const float* sp_W2  = (const float*)d_in[21];
    const float* sp_b2  = (const float*)d_in[22];

    int n = in_sizes[0] / 64;
    int E = in_sizes[2] / 2;

    float* delta = (float*)d_out;
    float* hf    = delta + (size_t)n * 64;
    float* pred  = hf + (size_t)n * 64;

    int nb64   = (n + 63) / 64;
    int nbN    = (n + 255) / 256;
    int nbE    = (E + 255) / 256;
    int nb1024 = (n + 1023) / 1024;
    int nbW    = (n * 32 + 255) / 256;

    const int ENC_SMEM = (576 + 4160 + 4160) * 4 + 1024 * 16;  // 51968
    const int FIN_SMEM = (8256 + 4160 + 4160) * 4 + 2048 * 16; // 99072
    cudaFuncSetAttribute(k_encgemm, cudaFuncAttributeMaxDynamicSharedMemorySize, ENC_SMEM);
    cudaFuncSetAttribute(k_final, cudaFuncAttributeMaxDynamicSharedMemorySize, FIN_SMEM);

    k_zero<<<nbN, 256>>>(n);
    k_cnt<<<nbE, 256>>>(ei, E);
    k_scanA<<<nb1024, 1024>>>(n);
    k_scanB<<<1, 128>>>(nb1024);
    k_scanC<<<nbN, 256>>>(n);
    k_csr<<<nbE, 256>>>(ei, E);
    k_encgemm<<<nb64, 256, ENC_SMEM>>>(ev, enc_W1, enc_b1, enc_W2, enc_b2, gcn_W, n);
    k_gcn_agg<<<nbW, 256>>>(gcn_b, n);
    k_gemm64v2<<<nb64, 256>>>(gat_W, n);
    k_gat_node<<<nbW, 256>>>(att_s, att_d, n);
    k_gat_agg<<<nbW, 256>>>(gat_b, n);
    k_final<<<nb64, 256, FIN_SMEM>>>(H, gate_W, gate_b, res_W1, res_b1, res_W2, res_b2,
                                     sp_W1, sp_b1, sp_W2, sp_b2, delta, hf, pred, n);
}